// round 11
// baseline (speedup 1.0000x reference)
#include <cuda_runtime.h>
#include <cuda_fp16.h>
#include <cstdint>
#include <cstddef>

#define NQ   65536
#define MS   65536
#define HN   32
#define CIN  64
#define CO   64
#define KP   15
#define KTOT 960            // KP * CIN
#define CHUNK_STRIDE ((size_t)NQ * 64)     // halves per weighted k-chunk

// ---- device scratch ----------------------------------------------------------
// weighted, CHUNK-MAJOR: element (q, k, i) at g_wt16[k*NQ*64 + q*64 + i]
__device__ __half g_wt16[(size_t)NQ * KTOT];
// W^T, CHUNK-MAJOR:      element (k, i, o) at g_Wt16[(k*CO + o)*64 + i]
__device__ __half g_Wt16[(size_t)CO * KTOT];
__device__ __half g_x16[(size_t)MS * CIN];     // x, fp16

__device__ float g_sums[CO];
__device__ float g_sumsq[CO];

// ---- helpers -------------------------------------------------------------------
static __device__ __forceinline__ float fast_sqrt(float x) {
    float r;
    asm("sqrt.approx.f32 %0, %1;" : "=f"(r) : "f"(x));
    return r;
}
static __device__ __forceinline__ void cp_async16(uint32_t smem_dst, const void* gmem_src) {
    asm volatile("cp.async.cg.shared.global [%0], [%1], 16;"
                 :: "r"(smem_dst), "l"(gmem_src));
}
static __device__ __forceinline__ void cp_commit() { asm volatile("cp.async.commit_group;"); }
static __device__ __forceinline__ void cp_wait0()  { asm volatile("cp.async.wait_group 0;"); }
static __device__ __forceinline__ void cp_wait1()  { asm volatile("cp.async.wait_group 1;"); }
static __device__ __forceinline__ void cp_wait2()  { asm volatile("cp.async.wait_group 2;"); }

static __device__ __forceinline__ uint32_t smem_u32(const void* p) {
    uint32_t a;
    asm("{ .reg .u64 t; cvta.to.shared.u64 t, %1; cvt.u32.u64 %0, t; }" : "=r"(a) : "l"(p));
    return a;
}

#define SWZ128(b)   ((b) ^ (((b) >> 3) & 0x70))

#define LDSM4(r0, r1, r2, r3, addr) \
    asm volatile("ldmatrix.sync.aligned.m8n8.x4.shared.b16 {%0,%1,%2,%3}, [%4];" \
        : "=r"(r0), "=r"(r1), "=r"(r2), "=r"(r3) : "r"(addr))

#define LDSM4T(r0, r1, r2, r3, addr) \
    asm volatile("ldmatrix.sync.aligned.m8n8.x4.trans.shared.b16 {%0,%1,%2,%3}, [%4];" \
        : "=r"(r0), "=r"(r1), "=r"(r2), "=r"(r3) : "r"(addr))

#define MMA16816F(c, a0, a1, a2, a3, b0, b1) \
    asm volatile("mma.sync.aligned.m16n8k16.row.col.f32.f16.f16.f32 " \
        "{%0,%1,%2,%3}, {%4,%5,%6,%7}, {%8,%9}, {%0,%1,%2,%3};" \
        : "+f"((c)[0]), "+f"((c)[1]), "+f"((c)[2]), "+f"((c)[3]) \
        : "r"(a0), "r"(a1), "r"(a2), "r"(a3), "r"(b0), "r"(b1))

// =============================================================================
// Kernel P1: x -> fp16
// =============================================================================
__global__ void __launch_bounds__(256)
prep_x16(const float* __restrict__ x) {
    const int i = blockIdx.x * 256 + threadIdx.x;
    g_x16[i] = __float2half(x[i]);
}

// =============================================================================
// Kernel P2: transpose W -> chunk-major Wt[(k*CO+o)*64 + i] fp16
// =============================================================================
__global__ void __launch_bounds__(64)
prep_w(const float* __restrict__ Wg) {
    const int ki = blockIdx.x;              // 0..959 = k*64 + i
    const int o  = threadIdx.x;             // 0..63
    const int k  = ki >> 6;
    const int i  = ki & 63;
    g_Wt16[((size_t)(k * CO + o)) * 64 + i] = __float2half(Wg[ki * 64 + o]);
}

// =============================================================================
// Kernel A: HMMA aggregation (R10 structure, unchanged numerics)
//   epilogue writes weighted in CHUNK-MAJOR layout
// =============================================================================
#define QW       8
#define AGW      10752u
#define AG_XB(b) ((b) * 4096u)
#define AG_IH    8192u
#define AG_IL    9472u
#define AGG_SMEM (4 * AGW)

__global__ void __launch_bounds__(128)
kpconv_aggregate_tc(const float* __restrict__ q_pts,
                    const float* __restrict__ s_pts,
                    const int*   __restrict__ nbr,
                    const float* __restrict__ kp)
{
    extern __shared__ char smA[];
    __shared__ float4 kp4s[16];

    const int tid  = threadIdx.x;
    const int warp = tid >> 5;
    const int lane = tid & 31;
    const uint32_t wb = smem_u32(smA) + warp * AGW;

    if (blockIdx.x == 0 && tid < CO) { g_sums[tid] = 0.f; g_sumsq[tid] = 0.f; }

    if (tid < 16) {
        float4 v = make_float4(0.f, 0.f, 0.f, 0.f);
        if (tid < KP) {
            v.x = kp[tid * 3 + 0];
            v.y = kp[tid * 3 + 1];
            v.z = kp[tid * 3 + 2];
        }
        kp4s[tid] = v;
    }
    __syncthreads();

    const double EXT_D = 0.1 * 1.2 / 2.5;
    const float  INV_E = (float)(1.0 / EXT_D);

    const int q0 = (blockIdx.x * 4 + warp) * QW;

    const int krow_base  = (lane & 7) + ((lane >> 3) & 1) * 8;
    const uint32_t a_off = (uint32_t)((lane & 15) * 80 + (lane >> 4) * 16);
    const int kp0 = lane >> 2;
    const int kp1 = kp0 + 8;
    const int cb  = 2 * (lane & 3);

    int idx_cur = nbr[q0 * HN + lane];
    #pragma unroll
    for (int i = 0; i < 8; ++i) {
        const int v = i * 32 + lane;
        const int r = v >> 3, u = v & 7;
        const int ir = __shfl_sync(0xffffffffu, idx_cur, r);
        cp_async16(wb + AG_XB(0) + SWZ128((uint32_t)(r * 128 + u * 16)),
                   g_x16 + (size_t)ir * CIN + u * 8);
    }
    cp_commit();

    #pragma unroll 1
    for (int qi = 0; qi < QW; ++qi) {
        const int q = q0 + qi;

        int idx_next = 0;
        if (qi + 1 < QW) {
            idx_next = nbr[(q + 1) * HN + lane];
            const uint32_t xb = wb + AG_XB((qi + 1) & 1);
            #pragma unroll
            for (int i = 0; i < 8; ++i) {
                const int v = i * 32 + lane;
                const int r = v >> 3, u = v & 7;
                const int ir = __shfl_sync(0xffffffffu, idx_next, r);
                cp_async16(xb + SWZ128((uint32_t)(r * 128 + u * 16)),
                           g_x16 + (size_t)ir * CIN + u * 8);
            }
            cp_commit();
        }

        const float qx = q_pts[q * 3 + 0];
        const float qy = q_pts[q * 3 + 1];
        const float qz = q_pts[q * 3 + 2];
        const float rx = s_pts[idx_cur * 3 + 0] - qx;
        const float ry = s_pts[idx_cur * 3 + 1] - qy;
        const float rz = s_pts[idx_cur * 3 + 2] - qz;

        #pragma unroll
        for (int k = 0; k < 16; ++k) {
            float w = 0.f;
            if (k < KP) {
                float4 kv = kp4s[k];
                float dx = rx - kv.x, dy = ry - kv.y, dz = rz - kv.z;
                float d2 = fmaf(dx, dx, fmaf(dy, dy, dz * dz));
                float s  = fast_sqrt(d2);
                w = fmaxf(fmaf(s, -INV_E, 1.f), 0.f);
            }
            __half h = __float2half(w);
            __half l = __float2half(w - __half2float(h));
            asm volatile("st.shared.b16 [%0], %1;"
                         :: "r"(wb + AG_IH + k * 80 + lane * 2),
                            "h"(*(unsigned short*)&h) : "memory");
            asm volatile("st.shared.b16 [%0], %1;"
                         :: "r"(wb + AG_IL + k * 80 + lane * 2),
                            "h"(*(unsigned short*)&l) : "memory");
        }
        __syncwarp();

        if (qi + 1 < QW) cp_wait1(); else cp_wait0();
        __syncwarp();

        const uint32_t xb = wb + AG_XB(qi & 1);

        float acc[8][4];
        #pragma unroll
        for (int t = 0; t < 8; ++t)
            #pragma unroll
            for (int e = 0; e < 4; ++e) acc[t][e] = 0.f;

        #pragma unroll
        for (int s = 0; s < 2; ++s) {
            uint32_t ah0, ah1, ah2, ah3, al0, al1, al2, al3;
            LDSM4(ah0, ah1, ah2, ah3, wb + AG_IH + a_off + s * 32);
            LDSM4(al0, al1, al2, al3, wb + AG_IL + a_off + s * 32);

            const int krow = s * 16 + krow_base;
            #pragma unroll
            for (int t = 0; t < 4; ++t) {
                const uint32_t boff =
                    SWZ128((uint32_t)(krow * 128 + t * 32 + ((lane >> 4) * 16)));
                uint32_t b0, b1, b2, b3;
                LDSM4T(b0, b1, b2, b3, xb + boff);

                MMA16816F(acc[2 * t],     ah0, ah1, ah2, ah3, b0, b1);
                MMA16816F(acc[2 * t],     al0, al1, al2, al3, b0, b1);
                MMA16816F(acc[2 * t + 1], ah0, ah1, ah2, ah3, b2, b3);
                MMA16816F(acc[2 * t + 1], al0, al1, al2, al3, b2, b3);
            }
        }
        __syncwarp();

        // ---- epilogue: weighted -> fp16, CHUNK-MAJOR ----
        __half* base = g_wt16 + (size_t)q * 64;
        #pragma unroll
        for (int t = 0; t < 8; ++t) {
            const int c = t * 8 + cb;
            *(__half2*)(base + (size_t)kp0 * CHUNK_STRIDE + c) =
                __floats2half2_rn(acc[t][0], acc[t][1]);
            if (kp1 < KP)
                *(__half2*)(base + (size_t)kp1 * CHUNK_STRIDE + c) =
                    __floats2half2_rn(acc[t][2], acc[t][3]);
        }

        idx_cur = idx_next;
    }
}

// =============================================================================
// Kernel B: HMMA GEMM, chunk-major streaming loads, 3-stage pipeline
// =============================================================================
#define HB_A(b)  ((b) * 24576u)
#define HB_W(b)  ((b) * 24576u + 16384u)
#define HB_RED   73728u
#define HB_TOTAL (73728 + 512)

extern __shared__ char smH[];

static __device__ __forceinline__ void load_chunk(uint32_t sb, int buf, int qbase, int c,
                                                  int tid) {
    // A: contiguous within chunk: base = c*NQ*64 + (qbase+row)*64
    const __half* asrc = g_wt16 + (size_t)c * CHUNK_STRIDE + (size_t)qbase * 64;
    #pragma unroll
    for (int i = 0; i < 4; ++i) {
        const int v = i * 256 + tid;
        const int row = v >> 3, u = v & 7;
        const uint32_t d = SWZ128((uint32_t)(row * 128 + u * 16));
        cp_async16(sb + HB_A(buf) + d, asrc + row * 64 + u * 8);
    }
    // W: contiguous 8KB per chunk: (c*CO + row)*64
    const __half* wsrc = g_Wt16 + (size_t)c * CO * 64;
    #pragma unroll
    for (int i = 0; i < 2; ++i) {
        const int v = i * 256 + tid;
        const int row = v >> 3, u = v & 7;
        const uint32_t d = SWZ128((uint32_t)(row * 128 + u * 16));
        cp_async16(sb + HB_W(buf) + d, wsrc + row * 64 + u * 8);
    }
    cp_commit();
}

__global__ void __launch_bounds__(256, 3)
kpconv_gemm_hmma(float* __restrict__ out)
{
    const uint32_t sb = smem_u32(smH);
    const int tid   = threadIdx.x;
    const int warp  = tid >> 5;
    const int lane  = tid & 31;
    const int qbase = blockIdx.x * 128;

    float* red  = (float*)(smH + HB_RED);
    float* red2 = red + 64;
    if (tid < 128) red[tid] = 0.f;

    const int a_row = warp * 16 + (lane & 15);
    const int a_cb  = (lane >> 4) * 16;
    const int b_row = (lane & 7) + ((lane >> 4) << 3);
    const int b_cb  = ((lane >> 3) & 1) * 16;

    float acc[8][4];
    #pragma unroll
    for (int t = 0; t < 8; ++t)
        #pragma unroll
        for (int e = 0; e < 4; ++e) acc[t][e] = 0.f;

    load_chunk(sb, 0, qbase, 0, tid);
    load_chunk(sb, 1, qbase, 1, tid);
    load_chunk(sb, 2, qbase, 2, tid);

    int buf = 0;
    #pragma unroll 1
    for (int c = 0; c < 15; ++c) {
        if (c <= 12)      cp_wait2();
        else if (c == 13) cp_wait1();
        else              cp_wait0();
        __syncthreads();

        const uint32_t ab  = sb + HB_A(buf);
        const uint32_t wbm = sb + HB_W(buf);

        #pragma unroll
        for (int s = 0; s < 4; ++s) {
            const uint32_t aoff = SWZ128((uint32_t)(a_row * 128 + s * 32 + a_cb));
            uint32_t a0, a1, a2, a3;
            LDSM4(a0, a1, a2, a3, ab + aoff);

            #pragma unroll
            for (int p = 0; p < 4; ++p) {
                const uint32_t boff =
                    SWZ128((uint32_t)((p * 16 + b_row) * 128 + s * 32 + b_cb));
                uint32_t b0, b1, b2, b3;
                LDSM4(b0, b1, b2, b3, wbm + boff);
                MMA16816F(acc[2 * p],     a0, a1, a2, a3, b0, b1);
                MMA16816F(acc[2 * p + 1], a0, a1, a2, a3, b2, b3);
            }
        }

        __syncthreads();
        if (c + 3 < 15) load_chunk(sb, buf, qbase, c + 3, tid);
        buf = (buf == 2) ? 0 : buf + 1;
    }

    // ---- epilogue: write + BN partials ----
    const int tm = lane >> 2;
    const int tn = (lane & 3) * 2;
    const int n0 = qbase + warp * 16 + tm;
    #pragma unroll
    for (int t = 0; t < 8; ++t) {
        const int col = t * 8 + tn;
        *(float2*)(out + (size_t)n0 * CO + col)       = make_float2(acc[t][0], acc[t][1]);
        *(float2*)(out + (size_t)(n0 + 8) * CO + col) = make_float2(acc[t][2], acc[t][3]);
        atomicAdd(red  + col,     acc[t][0] + acc[t][2]);
        atomicAdd(red  + col + 1, acc[t][1] + acc[t][3]);
        atomicAdd(red2 + col,     fmaf(acc[t][0], acc[t][0], acc[t][2] * acc[t][2]));
        atomicAdd(red2 + col + 1, fmaf(acc[t][1], acc[t][1], acc[t][3] * acc[t][3]));
    }
    __syncthreads();
    if (tid < 64)       atomicAdd(&g_sums[tid], red[tid]);
    else if (tid < 128) atomicAdd(&g_sumsq[tid - 64], red2[tid - 64]);
}

// =============================================================================
// Kernel: BN finalize (per-block, redundant) + apply + LeakyReLU(0.1)
// =============================================================================
__global__ void __launch_bounds__(256)
bn_act_kernel(float* __restrict__ out,
              const float* __restrict__ gamma,
              const float* __restrict__ beta) {
    __shared__ float sc[64], sbf[64];
    if (threadIdx.x < 64) {
        const int o = threadIdx.x;
        const float invN = 1.f / (float)NQ;
        float mean = g_sums[o] * invN;
        float var  = g_sumsq[o] * invN - mean * mean;
        float inv  = rsqrtf(var + 1e-5f);
        float s    = gamma[o] * inv;
        sc[o]  = s;
        sbf[o] = fmaf(-mean, s, beta[o]);
    }
    __syncthreads();

    const int i = blockIdx.x * 256 + threadIdx.x;
    float4 v = ((const float4*)out)[i];
    const int c = (i & 15) * 4;
    float r0 = fmaf(v.x, sc[c + 0], sbf[c + 0]);
    float r1 = fmaf(v.y, sc[c + 1], sbf[c + 1]);
    float r2 = fmaf(v.z, sc[c + 2], sbf[c + 2]);
    float r3 = fmaf(v.w, sc[c + 3], sbf[c + 3]);
    r0 = (r0 >= 0.f) ? r0 : 0.1f * r0;
    r1 = (r1 >= 0.f) ? r1 : 0.1f * r1;
    r2 = (r2 >= 0.f) ? r2 : 0.1f * r2;
    r3 = (r3 >= 0.f) ? r3 : 0.1f * r3;
    ((float4*)out)[i] = make_float4(r0, r1, r2, r3);
}

// =============================================================================
extern "C" void kernel_launch(void* const* d_in, const int* in_sizes, int n_in,
                              void* d_out, int out_size) {
    const float* x      = (const float*)d_in[0];
    const float* q_pts  = (const float*)d_in[1];
    const float* s_pts  = (const float*)d_in[2];
    const int*   nbr    = (const int*)d_in[3];
    const float* kp     = (const float*)d_in[4];
    const float* Wg     = (const float*)d_in[5];
    const float* gamma  = (const float*)d_in[6];
    const float* beta   = (const float*)d_in[7];
    float*       out    = (float*)d_out;

    cudaFuncSetAttribute(kpconv_gemm_hmma,
                         cudaFuncAttributeMaxDynamicSharedMemorySize, HB_TOTAL);

    prep_x16<<<(MS * CIN) / 256, 256>>>(x);
    prep_w<<<KTOT, 64>>>(Wg);
    kpconv_aggregate_tc<<<NQ / (4 * QW), 128, AGG_SMEM>>>(q_pts, s_pts, nbr, kp);
    kpconv_gemm_hmma<<<NQ / 128, 256, HB_TOTAL>>>(out);
    bn_act_kernel<<<(NQ * CO / 4) / 256, 256>>>(out, gamma, beta);
}